// round 15
// baseline (speedup 1.0000x reference)
#include <cuda_runtime.h>
#include <cuda_bf16.h>
#include <cstdint>
#include <math.h>

#define DIMC 1024
#define HEADS 16
#define HEAD_DIM 64
#define BATCH 2
#define TQ 2048
#define TK 2048
#define MROWS (BATCH * TQ) /* 4096 */

typedef __nv_bfloat16 bf16;

// ---------------------------------------------------------------------------
// Scratch (device globals: no alloc allowed)
// ---------------------------------------------------------------------------
__device__ bf16 g_qh[(size_t)MROWS * DIMC];
__device__ bf16 g_ql[(size_t)MROWS * DIMC];
__device__ bf16 g_kh[(size_t)MROWS * DIMC];
__device__ bf16 g_kl[(size_t)MROWS * DIMC];
__device__ bf16 g_vh[(size_t)MROWS * DIMC];
__device__ bf16 g_vl[(size_t)MROWS * DIMC];
__device__ bf16 g_wqh[(size_t)DIMC * DIMC];
__device__ bf16 g_wql[(size_t)DIMC * DIMC];
__device__ bf16 g_wkh[(size_t)DIMC * DIMC];
__device__ bf16 g_wkl[(size_t)DIMC * DIMC];
__device__ bf16 g_wvh[(size_t)DIMC * DIMC];
__device__ bf16 g_wvl[(size_t)DIMC * DIMC];
__device__ bf16 g_woh[(size_t)DIMC * DIMC];
__device__ bf16 g_wol[(size_t)DIMC * DIMC];
__device__ bf16 g_pqh[(size_t)MROWS * DIMC];
__device__ bf16 g_pql[(size_t)MROWS * DIMC];
__device__ bf16 g_pkh[(size_t)MROWS * DIMC];
__device__ bf16 g_pkl[(size_t)MROWS * DIMC];
__device__ bf16 g_pvh[(size_t)MROWS * DIMC];
__device__ bf16 g_pvl[(size_t)MROWS * DIMC];
__device__ bf16 g_aoh[(size_t)MROWS * DIMC];
__device__ bf16 g_aol[(size_t)MROWS * DIMC];
__device__ uint8_t g_mask8[(size_t)BATCH * TQ * TK];

// ---------------------------------------------------------------------------
// Helpers
// ---------------------------------------------------------------------------
__device__ __forceinline__ uint32_t smem_u32(const void* p) {
    uint32_t a;
    asm("{ .reg .u64 t; cvta.to.shared.u64 t, %1; cvt.u32.u64 %0, t; }" : "=r"(a) : "l"(p));
    return a;
}
__device__ __forceinline__ void cpa16(uint32_t dst, const void* src) {
    asm volatile("cp.async.cg.shared.global [%0], [%1], 16;" :: "r"(dst), "l"(src) : "memory");
}
#define CP_COMMIT() asm volatile("cp.async.commit_group;" ::: "memory")
#define CP_WAIT(n)  asm volatile("cp.async.wait_group %0;" :: "n"(n) : "memory")

__device__ __forceinline__ void ldsm_x4(uint32_t& r0, uint32_t& r1, uint32_t& r2, uint32_t& r3,
                                        uint32_t addr) {
    asm volatile("ldmatrix.sync.aligned.m8n8.x4.shared.b16 {%0,%1,%2,%3}, [%4];"
                 : "=r"(r0), "=r"(r1), "=r"(r2), "=r"(r3) : "r"(addr));
}
__device__ __forceinline__ void ldsm_x4_t(uint32_t& r0, uint32_t& r1, uint32_t& r2, uint32_t& r3,
                                          uint32_t addr) {
    asm volatile("ldmatrix.sync.aligned.m8n8.x4.trans.shared.b16 {%0,%1,%2,%3}, [%4];"
                 : "=r"(r0), "=r"(r1), "=r"(r2), "=r"(r3) : "r"(addr));
}
__device__ __forceinline__ void mma16816(float* c, uint32_t a0, uint32_t a1, uint32_t a2,
                                         uint32_t a3, uint32_t b0, uint32_t b1) {
    asm volatile(
        "mma.sync.aligned.m16n8k16.row.col.f32.bf16.bf16.f32 "
        "{%0,%1,%2,%3}, {%4,%5,%6,%7}, {%8,%9}, {%0,%1,%2,%3};"
        : "+f"(c[0]), "+f"(c[1]), "+f"(c[2]), "+f"(c[3])
        : "r"(a0), "r"(a1), "r"(a2), "r"(a3), "r"(b0), "r"(b1));
}
__device__ __forceinline__ uint32_t pack_hi(float a, float b) {
    __nv_bfloat162 h = __floats2bfloat162_rn(a, b);
    return *(uint32_t*)&h;
}
__device__ __forceinline__ uint32_t pack_lo(float a, float b) {
    float ra = a - __bfloat162float(__float2bfloat16(a));
    float rb = b - __bfloat162float(__float2bfloat16(b));
    __nv_bfloat162 h = __floats2bfloat162_rn(ra, rb);
    return *(uint32_t*)&h;
}

// ---------------------------------------------------------------------------
// Prep kernels.
// Main-stream: z = 0..2 act splits, 3..5 wq/wk/wv splits.
// Side-stream: z = 0 mask->u8, z = 1 wo split.
// ---------------------------------------------------------------------------
__device__ __forceinline__ void split_one(const float* __restrict__ src,
                                          bf16* __restrict__ hi, bf16* __restrict__ lo,
                                          int n) {
    int i = (blockIdx.x * blockDim.x + threadIdx.x) * 4;
    if (i >= n) return;
    float4 v = *(const float4*)(src + i);
    *(uint32_t*)(hi + i) = pack_hi(v.x, v.y);
    *(uint32_t*)(hi + i + 2) = pack_hi(v.z, v.w);
    *(uint32_t*)(lo + i) = pack_lo(v.x, v.y);
    *(uint32_t*)(lo + i + 2) = pack_lo(v.z, v.w);
}

__global__ void prep_main(const float* __restrict__ q, const float* __restrict__ k,
                          const float* __restrict__ v,
                          const float* __restrict__ wq, const float* __restrict__ wk,
                          const float* __restrict__ wv,
                          bf16* qh, bf16* ql, bf16* kh, bf16* kl, bf16* vh, bf16* vl,
                          bf16* wqh, bf16* wql, bf16* wkh, bf16* wkl,
                          bf16* wvh, bf16* wvl)
{
    const int z = blockIdx.z;
    if (z < 3) {
        const float* s = (z == 0) ? q : (z == 1) ? k : v;
        bf16* h = (z == 0) ? qh : (z == 1) ? kh : vh;
        bf16* l = (z == 0) ? ql : (z == 1) ? kl : vl;
        split_one(s, h, l, MROWS * DIMC);
    } else {
        const int w = z - 3;
        const float* s = (w == 0) ? wq : (w == 1) ? wk : wv;
        bf16* h = (w == 0) ? wqh : (w == 1) ? wkh : wvh;
        bf16* l = (w == 0) ? wql : (w == 1) ? wkl : wvl;
        split_one(s, h, l, DIMC * DIMC);
    }
}

__global__ void prep_side(const int* __restrict__ mask, const float* __restrict__ wo,
                          uint8_t* __restrict__ m8, bf16* woh, bf16* wol)
{
    if (blockIdx.z == 0) {
        const int n = BATCH * TQ * TK;
        int i = (blockIdx.x * blockDim.x + threadIdx.x) * 8;
        if (i >= n) return;
        int4 a = *(const int4*)(mask + i);
        int4 b = *(const int4*)(mask + i + 4);
        uint64_t vv = (uint64_t)(a.x != 0) | ((uint64_t)(a.y != 0) << 8) |
                      ((uint64_t)(a.z != 0) << 16) | ((uint64_t)(a.w != 0) << 24) |
                      ((uint64_t)(b.x != 0) << 32) | ((uint64_t)(b.y != 0) << 40) |
                      ((uint64_t)(b.z != 0) << 48) | ((uint64_t)(b.w != 0) << 56);
        *(uint64_t*)(m8 + i) = vv;
    } else {
        split_one(wo, woh, wol, DIMC * DIMC);
    }
}

// ---------------------------------------------------------------------------
// HMMA bf16-split NT GEMM — fused passes, 512 threads, CTA 256x128,
// warp tile 32x64, BK=64, 2-stage pipeline. (R9/R12-exact)
// ---------------------------------------------------------------------------
#define GPITCH 72
#define GPITCHB (GPITCH * 2)
#define AH_OFF 0
#define AL_OFF (256 * GPITCHB)
#define BH_OFF (2 * 256 * GPITCHB)
#define BL_OFF (BH_OFF + 128 * GPITCHB)
#define GSTAGE_B (BL_OFF + 128 * GPITCHB)    /* 110592 */
#define GEMM_SMEM (2 * GSTAGE_B)             /* 221184 */

__device__ __forceinline__ void ld_chunk_fused(
    uint32_t stage,
    const bf16* __restrict__ Ah, const bf16* __restrict__ Al,
    const bf16* __restrict__ Bh, const bf16* __restrict__ Bl,
    int bm, int bn, int ks, int K, int tid)
{
#pragma unroll
    for (int it = 0; it < 12; it++) {
        const int f = tid + it * 512;
        if (f < 2048) {
            const int r = f >> 3, c = f & 7;
            cpa16(stage + AH_OFF + r * GPITCHB + c * 16,
                  Ah + (size_t)(bm + r) * K + ks + c * 8);
        } else if (f < 4096) {
            const int u = f - 2048;
            const int r = u >> 3, c = u & 7;
            cpa16(stage + AL_OFF + r * GPITCHB + c * 16,
                  Al + (size_t)(bm + r) * K + ks + c * 8);
        } else if (f < 5120) {
            const int u = f - 4096;
            const int r = u >> 3, c = u & 7;
            cpa16(stage + BH_OFF + r * GPITCHB + c * 16,
                  Bh + (size_t)(bn + r) * K + ks + c * 8);
        } else {
            const int u = f - 5120;
            const int r = u >> 3, c = u & 7;
            cpa16(stage + BL_OFF + r * GPITCHB + c * 16,
                  Bl + (size_t)(bn + r) * K + ks + c * 8);
        }
    }
}

template <bool SPLIT>
__device__ __forceinline__ void gemm_mma_body(
    const bf16* __restrict__ Ah, const bf16* __restrict__ Al,
    const bf16* __restrict__ Bh, const bf16* __restrict__ Bl,
    const float* __restrict__ bias, float* __restrict__ Cf,
    bf16* __restrict__ Chi, bf16* __restrict__ Clo,
    int M, int N, int K)
{
    extern __shared__ char gsm[];
    const uint32_t sb = smem_u32(gsm);

    const int tid = threadIdx.x;
    const int wid = tid >> 5;
    const int lane = tid & 31;
    const int wm = wid & 7;
    const int wn = wid >> 3;
    const int bm = blockIdx.y * 256;
    const int bn = blockIdx.x * 128;

    float acc[2][8][4];
#pragma unroll
    for (int mt = 0; mt < 2; mt++)
#pragma unroll
        for (int j = 0; j < 8; j++)
#pragma unroll
            for (int q = 0; q < 4; q++) acc[mt][j][q] = 0.0f;

    const int nch = K >> 6;

    const int lrow = (lane & 7) + (((lane >> 3) & 1) << 3);
    const int lk8 = ((lane >> 4) & 1) << 3;

    auto st = [&](int s) { return sb + (uint32_t)s * GSTAGE_B; };

    ld_chunk_fused(st(0), Ah, Al, Bh, Bl, bm, bn, 0, K, tid);
    CP_COMMIT();
    CP_WAIT(0);
    __syncthreads();

    for (int c = 0; c < nch; c++) {
        const int cb = c & 1;
        const uint32_t base = st(cb);
        const bool have_next = (c + 1 < nch);
        if (have_next) {
            ld_chunk_fused(st(cb ^ 1), Ah, Al, Bh, Bl, bm, bn, (c + 1) << 6, K, tid);
            CP_COMMIT();
        }

#pragma unroll
        for (int k16 = 0; k16 < 4; k16++) {
            const uint32_t koff = (uint32_t)((k16 * 16 + lk8) * 2);
            const uint32_t arow = (uint32_t)((wm * 32 + lrow) * GPITCHB) + koff;
            const uint32_t brow = (uint32_t)((wn * 64 + lrow) * GPITCHB) + koff;

            uint32_t ahh[2][4], ahl[2][4], bb[8][2];
#pragma unroll
            for (int mt = 0; mt < 2; mt++)
                ldsm_x4(ahh[mt][0], ahh[mt][1], ahh[mt][2], ahh[mt][3],
                        base + AH_OFF + arow + (uint32_t)(mt * 16 * GPITCHB));
#pragma unroll
            for (int mt = 0; mt < 2; mt++)
                ldsm_x4(ahl[mt][0], ahl[mt][1], ahl[mt][2], ahl[mt][3],
                        base + AL_OFF + arow + (uint32_t)(mt * 16 * GPITCHB));
#pragma unroll
            for (int jp = 0; jp < 4; jp++) {
                uint32_t r0, r1, r2, r3;
                ldsm_x4(r0, r1, r2, r3,
                        base + BH_OFF + brow + (uint32_t)(jp * 16 * GPITCHB));
                bb[jp * 2 + 0][0] = r0; bb[jp * 2 + 0][1] = r2;
                bb[jp * 2 + 1][0] = r1; bb[jp * 2 + 1][1] = r3;
            }
#pragma unroll
            for (int mt = 0; mt < 2; mt++)
#pragma unroll
                for (int j = 0; j < 8; j++)
                    mma16816(acc[mt][j], ahh[mt][0], ahh[mt][1], ahh[mt][2], ahh[mt][3],
                             bb[j][0], bb[j][1]);
#pragma unroll
            for (int mt = 0; mt < 2; mt++)
#pragma unroll
                for (int j = 0; j < 8; j++)
                    mma16816(acc[mt][j], ahl[mt][0], ahl[mt][1], ahl[mt][2], ahl[mt][3],
                             bb[j][0], bb[j][1]);
#pragma unroll
            for (int jp = 0; jp < 4; jp++) {
                uint32_t r0, r1, r2, r3;
                ldsm_x4(r0, r1, r2, r3,
                        base + BL_OFF + brow + (uint32_t)(jp * 16 * GPITCHB));
                bb[jp * 2 + 0][0] = r0; bb[jp * 2 + 0][1] = r2;
                bb[jp * 2 + 1][0] = r1; bb[jp * 2 + 1][1] = r3;
            }
#pragma unroll
            for (int mt = 0; mt < 2; mt++)
#pragma unroll
                for (int j = 0; j < 8; j++)
                    mma16816(acc[mt][j], ahh[mt][0], ahh[mt][1], ahh[mt][2], ahh[mt][3],
                             bb[j][0], bb[j][1]);
        }

        if (have_next) CP_WAIT(0);
        __syncthreads();
    }

    const int g = lane >> 2;
    const int t = lane & 3;
#pragma unroll
    for (int mt = 0; mt < 2; mt++) {
        const int row0 = bm + wm * 32 + mt * 16 + g;
#pragma unroll
        for (int j = 0; j < 8; j++) {
            const int col = bn + wn * 64 + j * 8 + t * 2;
            const float b0 = bias[col], b1 = bias[col + 1];
            float f0 = acc[mt][j][0] + b0, f1 = acc[mt][j][1] + b1;
            float f2 = acc[mt][j][2] + b0, f3 = acc[mt][j][3] + b1;
            if (SPLIT) {
                *(uint32_t*)(Chi + (size_t)row0 * N + col) = pack_hi(f0, f1);
                *(uint32_t*)(Clo + (size_t)row0 * N + col) = pack_lo(f0, f1);
                *(uint32_t*)(Chi + (size_t)(row0 + 8) * N + col) = pack_hi(f2, f3);
                *(uint32_t*)(Clo + (size_t)(row0 + 8) * N + col) = pack_lo(f2, f3);
            } else {
                *(float2*)(Cf + (size_t)row0 * N + col) = make_float2(f0, f1);
                *(float2*)(Cf + (size_t)(row0 + 8) * N + col) = make_float2(f2, f3);
            }
        }
    }
}

__global__ __launch_bounds__(512, 1) void gemm_mma_out(
    const bf16* __restrict__ Ah, const bf16* __restrict__ Al,
    const bf16* __restrict__ Bh, const bf16* __restrict__ Bl,
    const float* __restrict__ bias, float* __restrict__ C, int M, int N, int K)
{
    gemm_mma_body<false>(Ah, Al, Bh, Bl, bias, C, nullptr, nullptr, M, N, K);
}

__global__ __launch_bounds__(512, 1) void gemm_mma_qkv(
    const bf16* __restrict__ qh, const bf16* __restrict__ ql,
    const bf16* __restrict__ kh, const bf16* __restrict__ kl,
    const bf16* __restrict__ vh, const bf16* __restrict__ vl,
    const bf16* __restrict__ wqh, const bf16* __restrict__ wql,
    const bf16* __restrict__ wkh, const bf16* __restrict__ wkl,
    const bf16* __restrict__ wvh, const bf16* __restrict__ wvl,
    const float* __restrict__ bq, const float* __restrict__ bk, const float* __restrict__ bv,
    bf16* __restrict__ pqh, bf16* __restrict__ pql,
    bf16* __restrict__ pkh, bf16* __restrict__ pkl,
    bf16* __restrict__ pvh, bf16* __restrict__ pvl)
{
    const int z = blockIdx.z;
    const bf16* Ah = (z == 0) ? qh : (z == 1) ? kh : vh;
    const bf16* Al = (z == 0) ? ql : (z == 1) ? kl : vl;
    const bf16* Bh = (z == 0) ? wqh : (z == 1) ? wkh : wvh;
    const bf16* Bl = (z == 0) ? wql : (z == 1) ? wkl : wvl;
    const float* bias = (z == 0) ? bq : (z == 1) ? bk : bv;
    bf16* Chi = (z == 0) ? pqh : (z == 1) ? pkh : pvh;
    bf16* Clo = (z == 0) ? pql : (z == 1) ? pkl : pvl;
    gemm_mma_body<true>(Ah, Al, Bh, Bl, bias, nullptr, Chi, Clo, MROWS, DIMC, DIMC);
}

// ---------------------------------------------------------------------------
// HMMA flash attention — 64 q-rows per CTA, 128 threads, 3 CTAs/SM.
// ---------------------------------------------------------------------------
#define KVP 72
#define KV_STAGE_ELEMS (4 * 64 * KVP)
#define ATTN_SMEM (2 * KV_STAGE_ELEMS * 2)   /* 73728 */

__global__ __launch_bounds__(128, 3) void attn_mma(
    const bf16* __restrict__ Qh, const bf16* __restrict__ Ql,
    const bf16* __restrict__ Kh, const bf16* __restrict__ Kl,
    const bf16* __restrict__ Vh, const bf16* __restrict__ Vl,
    const uint8_t* __restrict__ mask8, bf16* __restrict__ Oh, bf16* __restrict__ Ol)
{
    extern __shared__ bf16 kv[];
    const uint32_t kvb = smem_u32(kv);
    const int tid = threadIdx.x;
    const int wid = tid >> 5;
    const int lane = tid & 31;
    const int t = lane & 3;
    const int g = lane >> 2;
    const int q0 = blockIdx.x * 64;
    const int h = blockIdx.y;
    const int b = blockIdx.z;

    const size_t rowg = (size_t)b * TQ + q0 + wid * 16 + g;
    const size_t rowg8 = rowg + 8;
    uint32_t aqh[4][4], aql[4][4];
#pragma unroll
    for (int c = 0; c < 4; c++) {
        const int col = h * HEAD_DIM + c * 16 + t * 2;
        aqh[c][0] = *(const uint32_t*)(Qh + rowg * DIMC + col);
        aqh[c][1] = *(const uint32_t*)(Qh + rowg8 * DIMC + col);
        aqh[c][2] = *(const uint32_t*)(Qh + rowg * DIMC + col + 8);
        aqh[c][3] = *(const uint32_t*)(Qh + rowg8 * DIMC + col + 8);
        aql[c][0] = *(const uint32_t*)(Ql + rowg * DIMC + col);
        aql[c][1] = *(const uint32_t*)(Ql + rowg8 * DIMC + col);
        aql[c][2] = *(const uint32_t*)(Ql + rowg * DIMC + col + 8);
        aql[c][3] = *(const uint32_t*)(Ql + rowg8 * DIMC + col + 8);
    }

    float m_[2] = { -1e30f, -1e30f };
    float l_[2] = { 0.0f, 0.0f };
    float acc_o[8][4];
#pragma unroll
    for (int j = 0; j < 8; j++)
#pragma unroll
        for (int q = 0; q < 4; q++) acc_o[j][q] = 0.0f;

    auto ld_kv = [&](int kt, int s) {
        const size_t rbase = (size_t)b * TK + kt * 64;
#pragma unroll
        for (int i = 0; i < 16; i++) {
            int f = tid + i * 128;
            int arr = f >> 9;
            int idx = f & 511;
            int r = idx >> 3, c8 = idx & 7;
            const bf16* src = (arr == 0) ? Kh : (arr == 1) ? Kl : (arr == 2) ? Vh : Vl;
            uint32_t dst = kvb + (uint32_t)(s * KV_STAGE_ELEMS + arr * (64 * KVP) +
                                            r * KVP + c8 * 8) * 2;
            cpa16(dst, src + (rbase + r) * DIMC + h * HEAD_DIM + c8 * 8);
        }
    };

    ld_kv(0, 0);
    CP_COMMIT();

    const int lrow = (lane & 7) + (((lane >> 3) & 1) << 3);
    const int lk8 = ((lane >> 4) & 1) << 3;
    const int trow = (lane & 7) + (((lane >> 3) & 1) << 3);
    const int tcol = ((lane >> 4) & 1) << 3;

    const size_t mrow0 = ((size_t)b * TQ + q0 + wid * 16 + g) * TK;
    const size_t mrow1 = mrow0 + 8 * TK;

    for (int kt = 0; kt < TK / 64; kt++) {
        const int cb = kt & 1;
        const int nb = cb ^ 1;
        if (kt + 1 < TK / 64) {
            ld_kv(kt + 1, nb);
            CP_COMMIT();
            CP_WAIT(1);
        } else {
            CP_WAIT(0);
        }
        __syncthreads();

        const uint32_t KHb = kvb + (uint32_t)(cb * KV_STAGE_ELEMS) * 2;
        const uint32_t KLb = KHb + (64 * KVP) * 2;
        const uint32_t VHb = KHb + (2 * 64 * KVP) * 2;
        const uint32_t VLb = KHb + (3 * 64 * KVP) * 2;

        float acc_s[8][4];
#pragma unroll
        for (int j = 0; j < 8; j++)
#pragma unroll
            for (int q = 0; q < 4; q++) acc_s[j][q] = 0.0f;

#pragma unroll
        for (int c = 0; c < 4; c++) {
            const uint32_t koff = (uint32_t)((c * 16 + lk8) * 2);
            uint32_t bfr[8][2];
#pragma unroll
            for (int jp = 0; jp < 4; jp++) {
                uint32_t addr = KHb + (uint32_t)((jp * 16 + lrow) * KVP) * 2 + koff;
                uint32_t r0, r1, r2, r3;
                ldsm_x4(r0, r1, r2, r3, addr);
                bfr[jp * 2 + 0][0] = r0; bfr[jp * 2 + 0][1] = r2;
                bfr[jp * 2 + 1][0] = r1; bfr[jp * 2 + 1][1] = r3;
            }
#pragma unroll
            for (int j = 0; j < 8; j++)
                mma16816(acc_s[j], aqh[c][0], aqh[c][1], aqh[c][2], aqh[c][3],
                         bfr[j][0], bfr[j][1]);
#pragma unroll
            for (int j = 0; j < 8; j++)
                mma16816(acc_s[j], aql[c][0], aql[c][1], aql[c][2], aql[c][3],
                         bfr[j][0], bfr[j][1]);
#pragma unroll
            for (int jp = 0; jp < 4; jp++) {
                uint32_t addr = KLb + (uint32_t)((jp * 16 + lrow) * KVP) * 2 + koff;
                uint32_t r0, r1, r2, r3;
                ldsm_x4(r0, r1, r2, r3, addr);
                bfr[jp * 2 + 0][0] = r0; bfr[jp * 2 + 0][1] = r2;
                bfr[jp * 2 + 1][0] = r1; bfr[jp * 2 + 1][1] = r3;
            }
#pragma unroll
            for (int j = 0; j < 8; j++)
                mma16816(acc_s[j], aqh[c][0], aqh[c][1], aqh[c][2], aqh[c][3],
                         bfr[j][0], bfr[j][1]);
        }

        const int kc0 = kt * 64;
#pragma unroll
        for (int r01 = 0; r01 < 2; r01++) {
            const size_t mrow = ((r01 == 0) ? mrow0 : mrow1) + kc0;
            float mx = -1e30f;
#pragma unroll
            for (int j = 0; j < 8; j++) {
                uchar2 mm = *(const uchar2*)(mask8 + mrow + j * 8 + t * 2);
                float s0 = fminf(fmaxf(acc_s[j][r01 * 2 + 0] * 0.125f, -100.0f), 100.0f);
                float s1 = fminf(fmaxf(acc_s[j][r01 * 2 + 1] * 0.125f, -100.0f), 100.0f);
                s0 = mm.x ? s0 : -1e30f;
                s1 = mm.y ? s1 : -1e30f;
                acc_s[j][r01 * 2 + 0] = s0;
                acc_s[j][r01 * 2 + 1] = s1;
                mx = fmaxf(mx, fmaxf(s0, s1));
            }
            mx = fmaxf(mx, __shfl_xor_sync(0xffffffffu, mx, 1));
            mx = fmaxf(mx, __shfl_xor_sync(0xffffffffu, mx, 2));
            const float mnew = fmaxf(m_[r01], mx);
            const float alpha = __expf(m_[r01] - mnew);
            float rs = 0.0f;
#pragma unroll
            for (int j = 0; j < 8; j++) {
                float p0 = __expf(acc_s[j][r01 * 2 + 0] - mnew);
                float p1 = __expf(acc_s[j][r01 * 2 + 1] - mnew);
                acc_s[j][r01 * 2 + 0] = p0;
                acc_s[j][r01 * 2 + 1] = p1;
                rs += p0 + p1;
            }
            rs += __shfl_xor_sync(0xffffffffu, rs, 1);
            rs += __shfl_xor_sync(0xffffffffu, rs, 2);
            l_[r01] = l_[r01] * alpha + rs;
            m_[r01] = mnew;
#pragma unroll
            for (int j = 0; j < 8; j++) {
                acc_o[j][r01 * 2 + 0] *= alpha;
                acc_o[j][r01 * 2 + 1] *= alpha;
            }
        }

#pragma unroll
        for (int c = 0; c < 4; c++) {
            uint32_t ph[4], pl[4];
            ph[0] = pack_hi(acc_s[2 * c][0], acc_s[2 * c][1]);
            ph[1] = pack_hi(acc_s[2 * c][2], acc_s[2 * c][3]);
            ph[2] = pack_hi(acc_s[2 * c + 1][0], acc_s[2 * c + 1][1]);
            ph[3] = pack_hi(acc_s[2 * c + 1][2], acc_s[2 * c + 1][3]);
            pl[0] = pack_lo(acc_s[2 * c][0], acc_s[2 * c][1]);
            pl[1] = pack_lo(acc_s[2 * c][2], acc_s[2 * c][3]);
            pl[2] = pack_lo(acc_s[2 * c + 1][0], acc_s[2 * c + 1][1]);
            pl[3] = pack_lo(acc_s[2 * c + 1][2], acc_s[2 * c + 1][3]);
#pragma unroll
            for (int u = 0; u < 4; u++) {
                const uint32_t off = (uint32_t)((c * 16 + trow) * KVP + u * 16 + tcol) * 2;
                uint32_t vh0, vh1, vh2, vh3, vl0, vl1, vl2, vl3;
                ldsm_x4_t(vh0, vh1, vh2, vh3, VHb + off);
                ldsm_x4_t(vl0, vl1, vl2, vl3, VLb + off);
                mma16816(acc_o[2 * u + 0], ph[0], ph[1], ph[2], ph[3], vh0, vh1);
                mma16816(acc_o[2 * u + 1], ph[0], ph[1], ph[2], ph[3], vh2, vh3);
                mma16816(acc_o[2 * u + 0], ph[0], ph[1], ph[2], ph[3], vl0, vl1);
                mma16816(acc_o[2 * u + 1], ph[0], ph[1], ph[2], ph[3], vl2, vl3);
                mma16816(acc_o[2 * u + 0], pl[0], pl[1], pl[2], pl[3], vh0, vh1);
                mma16816(acc_o[2 * u + 1], pl[0], pl[1], pl[2], pl[3], vh2, vh3);
            }
        }
        __syncthreads();
    }

    const float inv0 = 1.0f / l_[0];
    const float inv1 = 1.0f / l_[1];
#pragma unroll
    for (int j = 0; j < 8; j++) {
        const int col = h * HEAD_DIM + j * 8 + t * 2;
        float f0 = acc_o[j][0] * inv0, f1 = acc_o[j][1] * inv0;
        float f2 = acc_o[j][2] * inv1, f3 = acc_o[j][3] * inv1;
        *(uint32_t*)(Oh + rowg * DIMC + col) = pack_hi(f0, f1);
        *(uint32_t*)(Ol + rowg * DIMC + col) = pack_lo(f0, f1);
        *(uint32_t*)(Oh + rowg8 * DIMC + col) = pack_hi(f2, f3);
        *(uint32_t*)(Ol + rowg8 * DIMC + col) = pack_lo(f2, f3);
    }
}

// ---------------------------------------------------------------------------
extern "C" void kernel_launch(void* const* d_in, const int* in_sizes, int n_in,
                              void* d_out, int out_size)
{
    const float* query = (const float*)d_in[0];
    const float* key = (const float*)d_in[1];
    const float* value = (const float*)d_in[2];
    const int* mask = (const int*)d_in[3];
    const float* wq = (const float*)d_in[4];
    const float* wk = (const float*)d_in[5];
    const float* wv = (const float*)d_in[6];
    const float* wo = (const float*)d_in[7];
    const float* bq = (const float*)d_in[8];
    const float* bk = (const float*)d_in[9];
    const float* bv = (const float*)d_in[10];
    const float* bo = (const float*)d_in[11];

    bf16 *qh, *ql, *kh, *kl, *vh, *vl;
    bf16 *wqh, *wql, *wkh, *wkl, *wvh, *wvl, *woh, *wol;
    bf16 *pqh, *pql, *pkh, *pkl, *pvh, *pvl, *aoh, *aol;
    uint8_t* mask8;
    cudaGetSymbolAddress((void**)&qh, g_qh);   cudaGetSymbolAddress((void**)&ql, g_ql);
    cudaGetSymbolAddress((void**)&kh, g_kh);   cudaGetSymbolAddress((void**)&kl, g_kl);
    cudaGetSymbolAddress((void**)&vh, g_vh);   cudaGetSymbolAddress((void**)&vl, g_vl);
    cudaGetSymbolAddress((void**)&wqh, g_wqh); cudaGetSymbolAddress((void**)&wql, g_wql);
    cudaGetSymbolAddress((void**)&wkh, g_wkh); cudaGetSymbolAddress((void**)&wkl, g_wkl);
    cudaGetSymbolAddress((void**)&wvh, g_wvh); cudaGetSymbolAddress((void**)&wvl, g_wvl);
    cudaGetSymbolAddress((void**)&woh, g_woh); cudaGetSymbolAddress((void**)&wol, g_wol);
    cudaGetSymbolAddress((void**)&pqh, g_pqh); cudaGetSymbolAddress((void**)&pql, g_pql);
    cudaGetSymbolAddress((void**)&pkh, g_pkh); cudaGetSymbolAddress((void**)&pkl, g_pkl);
    cudaGetSymbolAddress((void**)&pvh, g_pvh); cudaGetSymbolAddress((void**)&pvl, g_pvl);
    cudaGetSymbolAddress((void**)&aoh, g_aoh); cudaGetSymbolAddress((void**)&aol, g_aol);
    cudaGetSymbolAddress((void**)&mask8, g_mask8);

    static int attr_set = 0;
    static cudaStream_t s_side;
    static cudaEvent_t e_fork, e_join;
    if (!attr_set) {
        cudaFuncSetAttribute(attn_mma, cudaFuncAttributeMaxDynamicSharedMemorySize, ATTN_SMEM);
        cudaFuncSetAttribute(gemm_mma_qkv, cudaFuncAttributeMaxDynamicSharedMemorySize, GEMM_SMEM);
        cudaFuncSetAttribute(gemm_mma_out, cudaFuncAttributeMaxDynamicSharedMemorySize, GEMM_SMEM);
        cudaStreamCreateWithFlags(&s_side, cudaStreamNonBlocking);
        cudaEventCreateWithFlags(&e_fork, cudaEventDisableTiming);
        cudaEventCreateWithFlags(&e_join, cudaEventDisableTiming);
        attr_set = 1;
    }

    // Fork: side stream handles mask->u8 + wo split, overlapped with
    // main-stream splits + QKV GEMM (which is tensor-bound, DRAM ~3%).
    cudaEventRecord(e_fork, 0);
    cudaStreamWaitEvent(s_side, e_fork, 0);
    {
        dim3 gside(4096, 1, 2);  // z=0: mask (8.39M ints / 8 / 256), z=1: wo split
        prep_side<<<gside, 256, 0, s_side>>>(mask, wo, mask8, woh, wol);
        cudaEventRecord(e_join, s_side);
    }

    // Main stream: act + wq/wk/wv splits (z 0-5), then QKV.
    dim3 gprep(4096, 1, 6);
    prep_main<<<gprep, 256>>>(query, key, value, wq, wk, wv,
                              qh, ql, kh, kl, vh, vl,
                              wqh, wql, wkh, wkl, wvh, wvl);

    dim3 gqkv(DIMC / 128, MROWS / 256, 3);
    gemm_mma_qkv<<<gqkv, 512, GEMM_SMEM>>>(qh, ql, kh, kl, vh, vl,
                                           wqh, wql, wkh, wkl, wvh, wvl,
                                           bq, bk, bv,
                                           pqh, pql, pkh, pkl, pvh, pvl);

    // Join: attention needs mask8 (and gemm_mma_out later needs woh/wol).
    cudaStreamWaitEvent(0, e_join, 0);

    dim3 gattn(TQ / 64, HEADS, BATCH);
    attn_mma<<<gattn, 128, ATTN_SMEM>>>(pqh, pql, pkh, pkl, pvh, pvl, mask8, aoh, aol);

    dim3 gout(DIMC / 128, MROWS / 256);
    gemm_mma_out<<<gout, 512, GEMM_SMEM>>>(aoh, aol, woh, wol, bo, (float*)d_out,
                                           MROWS, DIMC, DIMC);
}

// round 16
// speedup vs baseline: 1.0050x; 1.0050x over previous
#include <cuda_runtime.h>
#include <cuda_bf16.h>
#include <cstdint>
#include <math.h>

#define DIMC 1024
#define HEADS 16
#define HEAD_DIM 64
#define BATCH 2
#define TQ 2048
#define TK 2048
#define MROWS (BATCH * TQ) /* 4096 */

typedef __nv_bfloat16 bf16;

// ---------------------------------------------------------------------------
// Scratch (device globals: no alloc allowed)
// ---------------------------------------------------------------------------
__device__ bf16 g_qh[(size_t)MROWS * DIMC];
__device__ bf16 g_ql[(size_t)MROWS * DIMC];
__device__ bf16 g_kh[(size_t)MROWS * DIMC];
__device__ bf16 g_kl[(size_t)MROWS * DIMC];
__device__ bf16 g_vh[(size_t)MROWS * DIMC];
__device__ bf16 g_vl[(size_t)MROWS * DIMC];
__device__ bf16 g_wqh[(size_t)DIMC * DIMC];
__device__ bf16 g_wql[(size_t)DIMC * DIMC];
__device__ bf16 g_wkh[(size_t)DIMC * DIMC];
__device__ bf16 g_wkl[(size_t)DIMC * DIMC];
__device__ bf16 g_wvh[(size_t)DIMC * DIMC];
__device__ bf16 g_wvl[(size_t)DIMC * DIMC];
__device__ bf16 g_woh[(size_t)DIMC * DIMC];
__device__ bf16 g_wol[(size_t)DIMC * DIMC];
__device__ bf16 g_pqh[(size_t)MROWS * DIMC];
__device__ bf16 g_pql[(size_t)MROWS * DIMC];
__device__ bf16 g_pkh[(size_t)MROWS * DIMC];
__device__ bf16 g_pkl[(size_t)MROWS * DIMC];
__device__ bf16 g_pvh[(size_t)MROWS * DIMC];
__device__ bf16 g_pvl[(size_t)MROWS * DIMC];
__device__ bf16 g_aoh[(size_t)MROWS * DIMC];
__device__ bf16 g_aol[(size_t)MROWS * DIMC];
__device__ uint8_t g_mask8[(size_t)BATCH * TQ * TK];

// ---------------------------------------------------------------------------
// Helpers
// ---------------------------------------------------------------------------
__device__ __forceinline__ uint32_t smem_u32(const void* p) {
    uint32_t a;
    asm("{ .reg .u64 t; cvta.to.shared.u64 t, %1; cvt.u32.u64 %0, t; }" : "=r"(a) : "l"(p));
    return a;
}
__device__ __forceinline__ void cpa16(uint32_t dst, const void* src) {
    asm volatile("cp.async.cg.shared.global [%0], [%1], 16;" :: "r"(dst), "l"(src) : "memory");
}
#define CP_COMMIT() asm volatile("cp.async.commit_group;" ::: "memory")
#define CP_WAIT(n)  asm volatile("cp.async.wait_group %0;" :: "n"(n) : "memory")

__device__ __forceinline__ void ldsm_x4(uint32_t& r0, uint32_t& r1, uint32_t& r2, uint32_t& r3,
                                        uint32_t addr) {
    asm volatile("ldmatrix.sync.aligned.m8n8.x4.shared.b16 {%0,%1,%2,%3}, [%4];"
                 : "=r"(r0), "=r"(r1), "=r"(r2), "=r"(r3) : "r"(addr));
}
__device__ __forceinline__ void ldsm_x4_t(uint32_t& r0, uint32_t& r1, uint32_t& r2, uint32_t& r3,
                                          uint32_t addr) {
    asm volatile("ldmatrix.sync.aligned.m8n8.x4.trans.shared.b16 {%0,%1,%2,%3}, [%4];"
                 : "=r"(r0), "=r"(r1), "=r"(r2), "=r"(r3) : "r"(addr));
}
__device__ __forceinline__ void mma16816(float* c, uint32_t a0, uint32_t a1, uint32_t a2,
                                         uint32_t a3, uint32_t b0, uint32_t b1) {
    asm volatile(
        "mma.sync.aligned.m16n8k16.row.col.f32.bf16.bf16.f32 "
        "{%0,%1,%2,%3}, {%4,%5,%6,%7}, {%8,%9}, {%0,%1,%2,%3};"
        : "+f"(c[0]), "+f"(c[1]), "+f"(c[2]), "+f"(c[3])
        : "r"(a0), "r"(a1), "r"(a2), "r"(a3), "r"(b0), "r"(b1));
}
__device__ __forceinline__ uint32_t pack_hi(float a, float b) {
    __nv_bfloat162 h = __floats2bfloat162_rn(a, b);
    return *(uint32_t*)&h;
}
__device__ __forceinline__ uint32_t pack_lo(float a, float b) {
    float ra = a - __bfloat162float(__float2bfloat16(a));
    float rb = b - __bfloat162float(__float2bfloat16(b));
    __nv_bfloat162 h = __floats2bfloat162_rn(ra, rb);
    return *(uint32_t*)&h;
}

// ---------------------------------------------------------------------------
// Fused prep: z = 0..2 act splits, 3..6 weight splits, 7 mask->u8
// ---------------------------------------------------------------------------
__device__ __forceinline__ void split_one(const float* __restrict__ src,
                                          bf16* __restrict__ hi, bf16* __restrict__ lo,
                                          int n) {
    int i = (blockIdx.x * blockDim.x + threadIdx.x) * 4;
    if (i >= n) return;
    float4 v = *(const float4*)(src + i);
    *(uint32_t*)(hi + i) = pack_hi(v.x, v.y);
    *(uint32_t*)(hi + i + 2) = pack_hi(v.z, v.w);
    *(uint32_t*)(lo + i) = pack_lo(v.x, v.y);
    *(uint32_t*)(lo + i + 2) = pack_lo(v.z, v.w);
}

__global__ void prep_all(const float* __restrict__ q, const float* __restrict__ k,
                         const float* __restrict__ v,
                         const float* __restrict__ wq, const float* __restrict__ wk,
                         const float* __restrict__ wv, const float* __restrict__ wo,
                         const int* __restrict__ mask,
                         bf16* qh, bf16* ql, bf16* kh, bf16* kl, bf16* vh, bf16* vl,
                         bf16* wqh, bf16* wql, bf16* wkh, bf16* wkl,
                         bf16* wvh, bf16* wvl, bf16* woh, bf16* wol,
                         uint8_t* __restrict__ m8)
{
    const int z = blockIdx.z;
    if (z < 3) {
        const float* s = (z == 0) ? q : (z == 1) ? k : v;
        bf16* h = (z == 0) ? qh : (z == 1) ? kh : vh;
        bf16* l = (z == 0) ? ql : (z == 1) ? kl : vl;
        split_one(s, h, l, MROWS * DIMC);
    } else if (z < 7) {
        const int w = z - 3;
        const float* s = (w == 0) ? wq : (w == 1) ? wk : (w == 2) ? wv : wo;
        bf16* h = (w == 0) ? wqh : (w == 1) ? wkh : (w == 2) ? wvh : woh;
        bf16* l = (w == 0) ? wql : (w == 1) ? wkl : (w == 2) ? wvl : wol;
        split_one(s, h, l, DIMC * DIMC);
    } else {
        const int n = BATCH * TQ * TK;
        int i = (blockIdx.x * blockDim.x + threadIdx.x) * 8;
        if (i >= n) return;
        int4 a = *(const int4*)(mask + i);
        int4 b = *(const int4*)(mask + i + 4);
        uint64_t vv = (uint64_t)(a.x != 0) | ((uint64_t)(a.y != 0) << 8) |
                      ((uint64_t)(a.z != 0) << 16) | ((uint64_t)(a.w != 0) << 24) |
                      ((uint64_t)(b.x != 0) << 32) | ((uint64_t)(b.y != 0) << 40) |
                      ((uint64_t)(b.z != 0) << 48) | ((uint64_t)(b.w != 0) << 56);
        *(uint64_t*)(m8 + i) = vv;
    }
}

// ---------------------------------------------------------------------------
// HMMA bf16-split NT GEMM — fused passes, 512 threads, CTA 256x128,
// warp tile 32x64, BK=64, 2-stage pipeline.
// ---------------------------------------------------------------------------
#define GPITCH 72
#define GPITCHB (GPITCH * 2)
#define AH_OFF 0
#define AL_OFF (256 * GPITCHB)
#define BH_OFF (2 * 256 * GPITCHB)
#define BL_OFF (BH_OFF + 128 * GPITCHB)
#define GSTAGE_B (BL_OFF + 128 * GPITCHB)    /* 110592 */
#define GEMM_SMEM (2 * GSTAGE_B)             /* 221184 */

__device__ __forceinline__ void ld_chunk_fused(
    uint32_t stage,
    const bf16* __restrict__ Ah, const bf16* __restrict__ Al,
    const bf16* __restrict__ Bh, const bf16* __restrict__ Bl,
    int bm, int bn, int ks, int K, int tid)
{
#pragma unroll
    for (int it = 0; it < 12; it++) {
        const int f = tid + it * 512;
        if (f < 2048) {
            const int r = f >> 3, c = f & 7;
            cpa16(stage + AH_OFF + r * GPITCHB + c * 16,
                  Ah + (size_t)(bm + r) * K + ks + c * 8);
        } else if (f < 4096) {
            const int u = f - 2048;
            const int r = u >> 3, c = u & 7;
            cpa16(stage + AL_OFF + r * GPITCHB + c * 16,
                  Al + (size_t)(bm + r) * K + ks + c * 8);
        } else if (f < 5120) {
            const int u = f - 4096;
            const int r = u >> 3, c = u & 7;
            cpa16(stage + BH_OFF + r * GPITCHB + c * 16,
                  Bh + (size_t)(bn + r) * K + ks + c * 8);
        } else {
            const int u = f - 5120;
            const int r = u >> 3, c = u & 7;
            cpa16(stage + BL_OFF + r * GPITCHB + c * 16,
                  Bl + (size_t)(bn + r) * K + ks + c * 8);
        }
    }
}

template <bool SPLIT>
__device__ __forceinline__ void gemm_mma_body(
    const bf16* __restrict__ Ah, const bf16* __restrict__ Al,
    const bf16* __restrict__ Bh, const bf16* __restrict__ Bl,
    const float* __restrict__ bias, float* __restrict__ Cf,
    bf16* __restrict__ Chi, bf16* __restrict__ Clo,
    int M, int N, int K)
{
    extern __shared__ char gsm[];
    const uint32_t sb = smem_u32(gsm);

    const int tid = threadIdx.x;
    const int wid = tid >> 5;
    const int lane = tid & 31;
    const int wm = wid & 7;
    const int wn = wid >> 3;
    const int bm = blockIdx.y * 256;
    const int bn = blockIdx.x * 128;

    float acc[2][8][4];
#pragma unroll
    for (int mt = 0; mt < 2; mt++)
#pragma unroll
        for (int j = 0; j < 8; j++)
#pragma unroll
            for (int q = 0; q < 4; q++) acc[mt][j][q] = 0.0f;

    const int nch = K >> 6;

    const int lrow = (lane & 7) + (((lane >> 3) & 1) << 3);
    const int lk8 = ((lane >> 4) & 1) << 3;

    auto st = [&](int s) { return sb + (uint32_t)s * GSTAGE_B; };

    ld_chunk_fused(st(0), Ah, Al, Bh, Bl, bm, bn, 0, K, tid);
    CP_COMMIT();
    CP_WAIT(0);
    __syncthreads();

    for (int c = 0; c < nch; c++) {
        const int cb = c & 1;
        const uint32_t base = st(cb);
        const bool have_next = (c + 1 < nch);
        if (have_next) {
            ld_chunk_fused(st(cb ^ 1), Ah, Al, Bh, Bl, bm, bn, (c + 1) << 6, K, tid);
            CP_COMMIT();
        }

#pragma unroll
        for (int k16 = 0; k16 < 4; k16++) {
            const uint32_t koff = (uint32_t)((k16 * 16 + lk8) * 2);
            const uint32_t arow = (uint32_t)((wm * 32 + lrow) * GPITCHB) + koff;
            const uint32_t brow = (uint32_t)((wn * 64 + lrow) * GPITCHB) + koff;

            uint32_t ahh[2][4], ahl[2][4], bb[8][2];
#pragma unroll
            for (int mt = 0; mt < 2; mt++)
                ldsm_x4(ahh[mt][0], ahh[mt][1], ahh[mt][2], ahh[mt][3],
                        base + AH_OFF + arow + (uint32_t)(mt * 16 * GPITCHB));
#pragma unroll
            for (int mt = 0; mt < 2; mt++)
                ldsm_x4(ahl[mt][0], ahl[mt][1], ahl[mt][2], ahl[mt][3],
                        base + AL_OFF + arow + (uint32_t)(mt * 16 * GPITCHB));
#pragma unroll
            for (int jp = 0; jp < 4; jp++) {
                uint32_t r0, r1, r2, r3;
                ldsm_x4(r0, r1, r2, r3,
                        base + BH_OFF + brow + (uint32_t)(jp * 16 * GPITCHB));
                bb[jp * 2 + 0][0] = r0; bb[jp * 2 + 0][1] = r2;
                bb[jp * 2 + 1][0] = r1; bb[jp * 2 + 1][1] = r3;
            }
#pragma unroll
            for (int mt = 0; mt < 2; mt++)
#pragma unroll
                for (int j = 0; j < 8; j++)
                    mma16816(acc[mt][j], ahh[mt][0], ahh[mt][1], ahh[mt][2], ahh[mt][3],
                             bb[j][0], bb[j][1]);
#pragma unroll
            for (int mt = 0; mt < 2; mt++)
#pragma unroll
                for (int j = 0; j < 8; j++)
                    mma16816(acc[mt][j], ahl[mt][0], ahl[mt][1], ahl[mt][2], ahl[mt][3],
                             bb[j][0], bb[j][1]);
#pragma unroll
            for (int jp = 0; jp < 4; jp++) {
                uint32_t r0, r1, r2, r3;
                ldsm_x4(r0, r1, r2, r3,
                        base + BL_OFF + brow + (uint32_t)(jp * 16 * GPITCHB));
                bb[jp * 2 + 0][0] = r0; bb[jp * 2 + 0][1] = r2;
                bb[jp * 2 + 1][0] = r1; bb[jp * 2 + 1][1] = r3;
            }
#pragma unroll
            for (int mt = 0; mt < 2; mt++)
#pragma unroll
                for (int j = 0; j < 8; j++)
                    mma16816(acc[mt][j], ahh[mt][0], ahh[mt][1], ahh[mt][2], ahh[mt][3],
                             bb[j][0], bb[j][1]);
        }

        if (have_next) CP_WAIT(0);
        __syncthreads();
    }

    const int g = lane >> 2;
    const int t = lane & 3;
#pragma unroll
    for (int mt = 0; mt < 2; mt++) {
        const int row0 = bm + wm * 32 + mt * 16 + g;
#pragma unroll
        for (int j = 0; j < 8; j++) {
            const int col = bn + wn * 64 + j * 8 + t * 2;
            const float b0 = bias[col], b1 = bias[col + 1];
            float f0 = acc[mt][j][0] + b0, f1 = acc[mt][j][1] + b1;
            float f2 = acc[mt][j][2] + b0, f3 = acc[mt][j][3] + b1;
            if (SPLIT) {
                *(uint32_t*)(Chi + (size_t)row0 * N + col) = pack_hi(f0, f1);
                *(uint32_t*)(Clo + (size_t)row0 * N + col) = pack_lo(f0, f1);
                *(uint32_t*)(Chi + (size_t)(row0 + 8) * N + col) = pack_hi(f2, f3);
                *(uint32_t*)(Clo + (size_t)(row0 + 8) * N + col) = pack_lo(f2, f3);
            } else {
                *(float2*)(Cf + (size_t)row0 * N + col) = make_float2(f0, f1);
                *(float2*)(Cf + (size_t)(row0 + 8) * N + col) = make_float2(f2, f3);
            }
        }
    }
}

__global__ __launch_bounds__(512, 1) void gemm_mma_out(
    const bf16* __restrict__ Ah, const bf16* __restrict__ Al,
    const bf16* __restrict__ Bh, const bf16* __restrict__ Bl,
    const float* __restrict__ bias, float* __restrict__ C, int M, int N, int K)
{
    gemm_mma_body<false>(Ah, Al, Bh, Bl, bias, C, nullptr, nullptr, M, N, K);
}

__global__ __launch_bounds__(512, 1) void gemm_mma_qkv(
    const bf16* __restrict__ qh, const bf16* __restrict__ ql,
    const bf16* __restrict__ kh, const bf16* __restrict__ kl,
    const bf16* __restrict__ vh, const bf16* __restrict__ vl,
    const bf16* __restrict__ wqh, const bf16* __restrict__ wql,
    const bf16* __restrict__ wkh, const bf16* __restrict__ wkl,
    const bf16* __restrict__ wvh, const bf16* __restrict__ wvl,
    const float* __restrict__ bq, const float* __restrict__ bk, const float* __restrict__ bv,
    bf16* __restrict__ pqh, bf16* __restrict__ pql,
    bf16* __restrict__ pkh, bf16* __restrict__ pkl,
    bf16* __restrict__ pvh, bf16* __restrict__ pvl)
{
    const int z = blockIdx.z;
    const bf16* Ah = (z == 0) ? qh : (z == 1) ? kh : vh;
    const bf16* Al = (z == 0) ? ql : (z == 1) ? kl : vl;
    const bf16* Bh = (z == 0) ? wqh : (z == 1) ? wkh : wvh;
    const bf16* Bl = (z == 0) ? wql : (z == 1) ? wkl : wvl;
    const float* bias = (z == 0) ? bq : (z == 1) ? bk : bv;
    bf16* Chi = (z == 0) ? pqh : (z == 1) ? pkh : pvh;
    bf16* Clo = (z == 0) ? pql : (z == 1) ? pkl : pvl;
    gemm_mma_body<true>(Ah, Al, Bh, Bl, bias, nullptr, Chi, Clo, MROWS, DIMC, DIMC);
}

// ---------------------------------------------------------------------------
// HMMA flash attention — 64 q-rows per CTA, 128 threads, 3 CTAs/SM.
// ---------------------------------------------------------------------------
#define KVP 72
#define KV_STAGE_ELEMS (4 * 64 * KVP)
#define ATTN_SMEM (2 * KV_STAGE_ELEMS * 2)   /* 73728 */

__global__ __launch_bounds__(128, 3) void attn_mma(
    const bf16* __restrict__ Qh, const bf16* __restrict__ Ql,
    const bf16* __restrict__ Kh, const bf16* __restrict__ Kl,
    const bf16* __restrict__ Vh, const bf16* __restrict__ Vl,
    const uint8_t* __restrict__ mask8, bf16* __restrict__ Oh, bf16* __restrict__ Ol)
{
    extern __shared__ bf16 kv[];
    const uint32_t kvb = smem_u32(kv);
    const int tid = threadIdx.x;
    const int wid = tid >> 5;
    const int lane = tid & 31;
    const int t = lane & 3;
    const int g = lane >> 2;
    const int q0 = blockIdx.x * 64;
    const int h = blockIdx.y;
    const int b = blockIdx.z;

    const size_t rowg = (size_t)b * TQ + q0 + wid * 16 + g;
    const size_t rowg8 = rowg + 8;
    uint32_t aqh[4][4], aql[4][4];
#pragma unroll
    for (int c = 0; c < 4; c++) {
        const int col = h * HEAD_DIM + c * 16 + t * 2;
        aqh[c][0] = *(const uint32_t*)(Qh + rowg * DIMC + col);
        aqh[c][1] = *(const uint32_t*)(Qh + rowg8 * DIMC + col);
        aqh[c][2] = *(const uint32_t*)(Qh + rowg * DIMC + col + 8);
        aqh[c][3] = *(const uint32_t*)(Qh + rowg8 * DIMC + col + 8);
        aql[c][0] = *(const uint32_t*)(Ql + rowg * DIMC + col);
        aql[c][1] = *(const uint32_t*)(Ql + rowg8 * DIMC + col);
        aql[c][2] = *(const uint32_t*)(Ql + rowg * DIMC + col + 8);
        aql[c][3] = *(const uint32_t*)(Ql + rowg8 * DIMC + col + 8);
    }

    float m_[2] = { -1e30f, -1e30f };
    float l_[2] = { 0.0f, 0.0f };
    float acc_o[8][4];
#pragma unroll
    for (int j = 0; j < 8; j++)
#pragma unroll
        for (int q = 0; q < 4; q++) acc_o[j][q] = 0.0f;

    auto ld_kv = [&](int kt, int s) {
        const size_t rbase = (size_t)b * TK + kt * 64;
#pragma unroll
        for (int i = 0; i < 16; i++) {
            int f = tid + i * 128;
            int arr = f >> 9;
            int idx = f & 511;
            int r = idx >> 3, c8 = idx & 7;
            const bf16* src = (arr == 0) ? Kh : (arr == 1) ? Kl : (arr == 2) ? Vh : Vl;
            uint32_t dst = kvb + (uint32_t)(s * KV_STAGE_ELEMS + arr * (64 * KVP) +
                                            r * KVP + c8 * 8) * 2;
            cpa16(dst, src + (rbase + r) * DIMC + h * HEAD_DIM + c8 * 8);
        }
    };

    ld_kv(0, 0);
    CP_COMMIT();

    const int lrow = (lane & 7) + (((lane >> 3) & 1) << 3);
    const int lk8 = ((lane >> 4) & 1) << 3;
    const int trow = (lane & 7) + (((lane >> 3) & 1) << 3);
    const int tcol = ((lane >> 4) & 1) << 3;

    const size_t mrow0 = ((size_t)b * TQ + q0 + wid * 16 + g) * TK;
    const size_t mrow1 = mrow0 + 8 * TK;

    for (int kt = 0; kt < TK / 64; kt++) {
        const int cb = kt & 1;
        const int nb = cb ^ 1;
        if (kt + 1 < TK / 64) {
            ld_kv(kt + 1, nb);
            CP_COMMIT();
            CP_WAIT(1);
        } else {
            CP_WAIT(0);
        }
        __syncthreads();

        const uint32_t KHb = kvb + (uint32_t)(cb * KV_STAGE_ELEMS) * 2;
        const uint32_t KLb = KHb + (64 * KVP) * 2;
        const uint32_t VHb = KHb + (2 * 64 * KVP) * 2;
        const uint32_t VLb = KHb + (3 * 64 * KVP) * 2;

        float acc_s[8][4];
#pragma unroll
        for (int j = 0; j < 8; j++)
#pragma unroll
            for (int q = 0; q < 4; q++) acc_s[j][q] = 0.0f;

#pragma unroll
        for (int c = 0; c < 4; c++) {
            const uint32_t koff = (uint32_t)((c * 16 + lk8) * 2);
            uint32_t bfr[8][2];
#pragma unroll
            for (int jp = 0; jp < 4; jp++) {
                uint32_t addr = KHb + (uint32_t)((jp * 16 + lrow) * KVP) * 2 + koff;
                uint32_t r0, r1, r2, r3;
                ldsm_x4(r0, r1, r2, r3, addr);
                bfr[jp * 2 + 0][0] = r0; bfr[jp * 2 + 0][1] = r2;
                bfr[jp * 2 + 1][0] = r1; bfr[jp * 2 + 1][1] = r3;
            }
#pragma unroll
            for (int j = 0; j < 8; j++)
                mma16816(acc_s[j], aqh[c][0], aqh[c][1], aqh[c][2], aqh[c][3],
                         bfr[j][0], bfr[j][1]);
#pragma unroll
            for (int j = 0; j < 8; j++)
                mma16816(acc_s[j], aql[c][0], aql[c][1], aql[c][2], aql[c][3],
                         bfr[j][0], bfr[j][1]);
#pragma unroll
            for (int jp = 0; jp < 4; jp++) {
                uint32_t addr = KLb + (uint32_t)((jp * 16 + lrow) * KVP) * 2 + koff;
                uint32_t r0, r1, r2, r3;
                ldsm_x4(r0, r1, r2, r3, addr);
                bfr[jp * 2 + 0][0] = r0; bfr[jp * 2 + 0][1] = r2;
                bfr[jp * 2 + 1][0] = r1; bfr[jp * 2 + 1][1] = r3;
            }
#pragma unroll
            for (int j = 0; j < 8; j++)
                mma16816(acc_s[j], aqh[c][0], aqh[c][1], aqh[c][2], aqh[c][3],
                         bfr[j][0], bfr[j][1]);
        }

        const int kc0 = kt * 64;
#pragma unroll
        for (int r01 = 0; r01 < 2; r01++) {
            const size_t mrow = ((r01 == 0) ? mrow0 : mrow1) + kc0;
            float mx = -1e30f;
#pragma unroll
            for (int j = 0; j < 8; j++) {
                uchar2 mm = *(const uchar2*)(mask8 + mrow + j * 8 + t * 2);
                float s0 = fminf(fmaxf(acc_s[j][r01 * 2 + 0] * 0.125f, -100.0f), 100.0f);
                float s1 = fminf(fmaxf(acc_s[j][r01 * 2 + 1] * 0.125f, -100.0f), 100.0f);
                s0 = mm.x ? s0 : -1e30f;
                s1 = mm.y ? s1 : -1e30f;
                acc_s[j][r01 * 2 + 0] = s0;
                acc_s[j][r01 * 2 + 1] = s1;
                mx = fmaxf(mx, fmaxf(s0, s1));
            }
            mx = fmaxf(mx, __shfl_xor_sync(0xffffffffu, mx, 1));
            mx = fmaxf(mx, __shfl_xor_sync(0xffffffffu, mx, 2));
            const float mnew = fmaxf(m_[r01], mx);
            const float alpha = __expf(m_[r01] - mnew);
            float rs = 0.0f;
#pragma unroll
            for (int j = 0; j < 8; j++) {
                float p0 = __expf(acc_s[j][r01 * 2 + 0] - mnew);
                float p1 = __expf(acc_s[j][r01 * 2 + 1] - mnew);
                acc_s[j][r01 * 2 + 0] = p0;
                acc_s[j][r01 * 2 + 1] = p1;
                rs += p0 + p1;
            }
            rs += __shfl_xor_sync(0xffffffffu, rs, 1);
            rs += __shfl_xor_sync(0xffffffffu, rs, 2);
            l_[r01] = l_[r01] * alpha + rs;
            m_[r01] = mnew;
#pragma unroll
            for (int j = 0; j < 8; j++) {
                acc_o[j][r01 * 2 + 0] *= alpha;
                acc_o[j][r01 * 2 + 1] *= alpha;
            }
        }

#pragma unroll
        for (int c = 0; c < 4; c++) {
            uint32_t ph[4], pl[4];
            ph[0] = pack_hi(acc_s[2 * c][0], acc_s[2 * c][1]);
            ph[1] = pack_hi(acc_s[2 * c][2], acc_s[2 * c][3]);
            ph[2] = pack_hi(acc_s[2 * c + 1][0], acc_s[2 * c + 1][1]);
            ph[3] = pack_hi(acc_s[2 * c + 1][2], acc_s[2 * c + 1][3]);
            pl[0] = pack_lo(acc_s[2 * c][0], acc_s[2 * c][1]);
            pl[1] = pack_lo(acc_s[2 * c][2], acc_s[2 * c][3]);
            pl[2] = pack_lo(acc_s[2 * c + 1][0], acc_s[2 * c + 1][1]);
            pl[3] = pack_lo(acc_s[2 * c + 1][2], acc_s[2 * c + 1][3]);
#pragma unroll
            for (int u = 0; u < 4; u++) {
                const uint32_t off = (uint32_t)((c * 16 + trow) * KVP + u * 16 + tcol) * 2;
                uint32_t vh0, vh1, vh2, vh3, vl0, vl1, vl2, vl3;
                ldsm_x4_t(vh0, vh1, vh2, vh3, VHb + off);
                ldsm_x4_t(vl0, vl1, vl2, vl3, VLb + off);
                mma16816(acc_o[2 * u + 0], ph[0], ph[1], ph[2], ph[3], vh0, vh1);
                mma16816(acc_o[2 * u + 1], ph[0], ph[1], ph[2], ph[3], vh2, vh3);
                mma16816(acc_o[2 * u + 0], ph[0], ph[1], ph[2], ph[3], vl0, vl1);
                mma16816(acc_o[2 * u + 1], ph[0], ph[1], ph[2], ph[3], vl2, vl3);
                mma16816(acc_o[2 * u + 0], pl[0], pl[1], pl[2], pl[3], vh0, vh1);
                mma16816(acc_o[2 * u + 1], pl[0], pl[1], pl[2], pl[3], vh2, vh3);
            }
        }
        __syncthreads();
    }

    const float inv0 = 1.0f / l_[0];
    const float inv1 = 1.0f / l_[1];
#pragma unroll
    for (int j = 0; j < 8; j++) {
        const int col = h * HEAD_DIM + j * 8 + t * 2;
        float f0 = acc_o[j][0] * inv0, f1 = acc_o[j][1] * inv0;
        float f2 = acc_o[j][2] * inv1, f3 = acc_o[j][3] * inv1;
        *(uint32_t*)(Oh + rowg * DIMC + col) = pack_hi(f0, f1);
        *(uint32_t*)(Ol + rowg * DIMC + col) = pack_lo(f0, f1);
        *(uint32_t*)(Oh + rowg8 * DIMC + col) = pack_hi(f2, f3);
        *(uint32_t*)(Ol + rowg8 * DIMC + col) = pack_lo(f2, f3);
    }
}

// ---------------------------------------------------------------------------
extern "C" void kernel_launch(void* const* d_in, const int* in_sizes, int n_in,
                              void* d_out, int out_size)
{
    const float* query = (const float*)d_in[0];
    const float* key = (const float*)d_in[1];
    const float* value = (const float*)d_in[2];
    const int* mask = (const int*)d_in[3];
    const float* wq = (const float*)d_in[4];
    const float* wk = (const float*)d_in[5];
    const float* wv = (const float*)d_in[6];
    const float* wo = (const float*)d_in[7];
    const float* bq = (const float*)d_in[8];
    const float* bk = (const float*)d_in[9];
    const float* bv = (const float*)d_in[10];
    const float* bo = (const float*)d_in[11];

    bf16 *qh, *ql, *kh, *kl, *vh, *vl;
    bf16 *wqh, *wql, *wkh, *wkl, *wvh, *wvl, *woh, *wol;
    bf16 *pqh, *pql, *pkh, *pkl, *pvh, *pvl, *aoh, *aol;
    uint8_t* mask8;
    cudaGetSymbolAddress((void**)&qh, g_qh);   cudaGetSymbolAddress((void**)&ql, g_ql);
    cudaGetSymbolAddress((void**)&kh, g_kh);   cudaGetSymbolAddress((void**)&kl, g_kl);
    cudaGetSymbolAddress((void**)&vh, g_vh);   cudaGetSymbolAddress((void**)&vl, g_vl);
    cudaGetSymbolAddress((void**)&wqh, g_wqh); cudaGetSymbolAddress((void**)&wql, g_wql);
    cudaGetSymbolAddress((void**)&wkh, g_wkh); cudaGetSymbolAddress((void**)&wkl, g_wkl);
    cudaGetSymbolAddress((void**)&wvh, g_wvh); cudaGetSymbolAddress((void**)&wvl, g_wvl);
    cudaGetSymbolAddress((void**)&woh, g_woh); cudaGetSymbolAddress((void**)&wol, g_wol);
    cudaGetSymbolAddress((void**)&pqh, g_pqh); cudaGetSymbolAddress((void**)&pql, g_pql);
    cudaGetSymbolAddress((void**)&pkh, g_pkh); cudaGetSymbolAddress((void**)&pkl, g_pkl);
    cudaGetSymbolAddress((void**)&pvh, g_pvh); cudaGetSymbolAddress((void**)&pvl, g_pvl);
    cudaGetSymbolAddress((void**)&aoh, g_aoh); cudaGetSymbolAddress((void**)&aol, g_aol);
    cudaGetSymbolAddress((void**)&mask8, g_mask8);

    static int attr_set = 0;
    if (!attr_set) {
        cudaFuncSetAttribute(attn_mma, cudaFuncAttributeMaxDynamicSharedMemorySize, ATTN_SMEM);
        cudaFuncSetAttribute(gemm_mma_qkv, cudaFuncAttributeMaxDynamicSharedMemorySize, GEMM_SMEM);
        cudaFuncSetAttribute(gemm_mma_out, cudaFuncAttributeMaxDynamicSharedMemorySize, GEMM_SMEM);
        attr_set = 1;
    }

    // Fused prep: acts (z 0-2), weights (z 3-6), mask (z 7)
    dim3 gprep(4096, 1, 8);
    prep_all<<<gprep, 256>>>(query, key, value, wq, wk, wv, wo, mask,
                             qh, ql, kh, kl, vh, vl,
                             wqh, wql, wkh, wkl, wvh, wvl, woh, wol, mask8);

    dim3 gqkv(DIMC / 128, MROWS / 256, 3);
    gemm_mma_qkv<<<gqkv, 512, GEMM_SMEM>>>(qh, ql, kh, kl, vh, vl,
                                           wqh, wql, wkh, wkl, wvh, wvl,
                                           bq, bk, bv,
                                           pqh, pql, pkh, pkl, pvh, pvl);

    dim3 gattn(TQ / 64, HEADS, BATCH);
    attn_mma<<<gattn, 128, ATTN_SMEM>>>(pqh, pql, pkh, pkl, pvh, pvl, mask8, aoh, aol);

    dim3 gout(DIMC / 128, MROWS / 256);
    gemm_mma_out<<<gout, 512, GEMM_SMEM>>>(aoh, aol, woh, wol, bo, (float*)d_out,
                                           MROWS, DIMC, DIMC);
}